// round 4
// baseline (speedup 1.0000x reference)
#include <cuda_runtime.h>
#include <cuda_bf16.h>
#include <math.h>
#include <stdint.h>

#define BB 4
#define SS 2048
#define DD 1024
#define MT (BB*SS)   // 8192

// ---------------------------------------------------------------------------
// Scratch (device globals)
// ---------------------------------------------------------------------------
__device__ __align__(16) __nv_bfloat16 g_xh[(size_t)MT*DD], g_xl[(size_t)MT*DD];
__device__ __align__(16) __nv_bfloat16 g_Wth[(size_t)3*DD*DD], g_Wtl[(size_t)3*DD*DD];
__device__ __align__(16) __nv_bfloat16 g_Qh[(size_t)MT*DD], g_Ql[(size_t)MT*DD];
__device__ __align__(16) __nv_bfloat16 g_Kh[(size_t)MT*DD], g_Kl[(size_t)MT*DD];
__device__ __align__(16) float        g_V [(size_t)MT*DD];
__device__ __align__(16) __nv_bfloat16 g_Vth[(size_t)BB*DD*SS], g_Vtl[(size_t)BB*DD*SS];
__device__ __align__(16) float        g_P [(size_t)BB*SS*SS];
__device__ __align__(16) __nv_bfloat16 g_Ph[(size_t)BB*SS*SS], g_Pl[(size_t)BB*SS*SS];

// ---------------------------------------------------------------------------
// Helpers
// ---------------------------------------------------------------------------
__device__ __forceinline__ uint32_t smem_u32(const void* p) {
    uint32_t a;
    asm("{ .reg .u64 t; cvta.to.shared.u64 t, %1; cvt.u32.u64 %0, t; }"
        : "=r"(a) : "l"(p));
    return a;
}

// SW128 swizzle on byte offsets (128B rows): bits[6:4] ^= bits[9:7]
#define SWZ(o) ((uint32_t)(o) ^ ((((uint32_t)(o)) >> 3) & 0x70))

#define CP_ASYNC(dst, src) \
    asm volatile("cp.async.cg.shared.global [%0], [%1], 16;" \
                 :: "r"(dst), "l"(__cvta_generic_to_global(src)))
#define CP_COMMIT() asm volatile("cp.async.commit_group;")
#define CP_WAIT2()  asm volatile("cp.async.wait_group 2;")
#define CP_WAIT1()  asm volatile("cp.async.wait_group 1;")
#define CP_WAIT0()  asm volatile("cp.async.wait_group 0;")

#define LDM_X4(r, addr) \
    asm volatile("ldmatrix.sync.aligned.m8n8.x4.shared.b16 {%0,%1,%2,%3}, [%4];" \
        : "=r"((r)[0]), "=r"((r)[1]), "=r"((r)[2]), "=r"((r)[3]) : "r"(addr))

#define MMA(d, a, b0v, b1v) \
    asm volatile("mma.sync.aligned.m16n8k16.row.col.f32.bf16.bf16.f32 " \
        "{%0,%1,%2,%3}, {%4,%5,%6,%7}, {%8,%9}, {%0,%1,%2,%3};" \
        : "+f"((d)[0]), "+f"((d)[1]), "+f"((d)[2]), "+f"((d)[3]) \
        : "r"((a)[0]), "r"((a)[1]), "r"((a)[2]), "r"((a)[3]), "r"(b0v), "r"(b1v))

// bf16 2-term split: returns packed hi pair, writes packed lo pair
__device__ __forceinline__ uint32_t pack2(float a, float b, uint32_t& lo2) {
    __nv_bfloat16 ha = __float2bfloat16(a);
    __nv_bfloat16 hb = __float2bfloat16(b);
    __nv_bfloat16 la = __float2bfloat16(a - __bfloat162float(ha));
    __nv_bfloat16 lb = __float2bfloat16(b - __bfloat162float(hb));
    lo2 = (uint32_t)__bfloat16_as_ushort(la) | ((uint32_t)__bfloat16_as_ushort(lb) << 16);
    return (uint32_t)__bfloat16_as_ushort(ha) | ((uint32_t)__bfloat16_as_ushort(hb) << 16);
}

// ---------------------------------------------------------------------------
// SMEM: stage = A plane (128 rows x [hi64B|lo64B] = 16KB) + B plane (16KB)
// 3 stages x 32KB = 96KB -> 2 CTAs/SM
// ---------------------------------------------------------------------------
#define OFF_B  16384
#define STG    32768
#define SM_TOT (3*STG)   // 98304 bytes

// ---------------------------------------------------------------------------
// Load one BK=32 chunk via cp.async. Row = [hi(32bf16)|lo(32bf16)] = 128B.
// 8 x 16B per thread (4 A + 4 B).
// ---------------------------------------------------------------------------
__device__ __forceinline__ void load_chunk(
    uint32_t stg,
    const __nv_bfloat16* __restrict__ Ah, const __nv_bfloat16* __restrict__ Al, int lda,
    const __nv_bfloat16* __restrict__ Bh, const __nv_bfloat16* __restrict__ Bl, int ldb,
    int k0, int tid)
{
#pragma unroll
    for (int i = 0; i < 4; ++i) {
        int u = tid + i * 256;
        int row = u >> 3, q = u & 7, half = q >> 2, qq = q & 3;
        uint32_t off = SWZ(row * 128 + q * 16);
        const __nv_bfloat16* a = (half ? Al : Ah) + (size_t)row * lda + k0 + qq * 8;
        const __nv_bfloat16* b = (half ? Bl : Bh) + (size_t)row * ldb + k0 + qq * 8;
        CP_ASYNC(stg + off, a);
        CP_ASYNC(stg + OFF_B + off, b);
    }
}

// ---------------------------------------------------------------------------
// Compute one BK=32 chunk: warp tile 64x32, 3-term split, phased to limit
// register liveness: hi*hi -> hi*lo -> lo*hi.
// ---------------------------------------------------------------------------
__device__ __forceinline__ void compute_chunk(
    uint32_t stg, int wm, int wn, int lane, float (&acc)[4][4][4])
{
    const int rsel = lane & 15;
    const int csel = lane >> 4;
#pragma unroll
    for (int ks = 0; ks < 2; ++ks) {
        const uint32_t cb = ks * 32 + csel * 16;
        uint32_t ah[4][4], bh[2][4];
#pragma unroll
        for (int i = 0; i < 4; ++i)
            LDM_X4(ah[i], stg + SWZ((wm * 64 + i * 16 + rsel) * 128 + cb));
#pragma unroll
        for (int j2 = 0; j2 < 2; ++j2)
            LDM_X4(bh[j2], stg + OFF_B + SWZ((wn * 32 + j2 * 16 + rsel) * 128 + cb));
#pragma unroll
        for (int i = 0; i < 4; ++i)
#pragma unroll
            for (int j = 0; j < 4; ++j)
                MMA(acc[i][j], ah[i], bh[j >> 1][j & 1], bh[j >> 1][(j & 1) + 2]);
        {
            uint32_t bl[2][4];
#pragma unroll
            for (int j2 = 0; j2 < 2; ++j2)
                LDM_X4(bl[j2], stg + OFF_B + SWZ((wn * 32 + j2 * 16 + rsel) * 128 + 64 + cb));
#pragma unroll
            for (int i = 0; i < 4; ++i)
#pragma unroll
                for (int j = 0; j < 4; ++j)
                    MMA(acc[i][j], ah[i], bl[j >> 1][j & 1], bl[j >> 1][(j & 1) + 2]);
        }
        {
            uint32_t al[4][4];
#pragma unroll
            for (int i = 0; i < 4; ++i)
                LDM_X4(al[i], stg + SWZ((wm * 64 + i * 16 + rsel) * 128 + 64 + cb));
#pragma unroll
            for (int i = 0; i < 4; ++i)
#pragma unroll
                for (int j = 0; j < 4; ++j)
                    MMA(acc[i][j], al[i], bh[j >> 1][j & 1], bh[j >> 1][(j & 1) + 2]);
        }
    }
}

// ---------------------------------------------------------------------------
// Full GEMM mainloop: C[128,128] = sum over nCh chunks of BK=32. nCh >= 3.
// ---------------------------------------------------------------------------
__device__ __forceinline__ void gemm_hmma(
    const __nv_bfloat16* __restrict__ Ah, const __nv_bfloat16* __restrict__ Al, int lda,
    const __nv_bfloat16* __restrict__ Bh, const __nv_bfloat16* __restrict__ Bl, int ldb,
    int nCh, float (&acc)[4][4][4], uint32_t sb, int tid)
{
    const int lane = tid & 31, w = tid >> 5;
    const int wm = w & 1, wn = w >> 1;

#pragma unroll
    for (int i = 0; i < 4; ++i)
#pragma unroll
        for (int j = 0; j < 4; ++j)
#pragma unroll
            for (int q = 0; q < 4; ++q) acc[i][j][q] = 0.f;

    load_chunk(sb + 0 * STG, Ah, Al, lda, Bh, Bl, ldb, 0, tid);
    CP_COMMIT();
    load_chunk(sb + 1 * STG, Ah, Al, lda, Bh, Bl, ldb, 32, tid);
    CP_COMMIT();
    load_chunk(sb + 2 * STG, Ah, Al, lda, Bh, Bl, ldb, 64, tid);
    CP_COMMIT();

    uint32_t slot = 0;
    for (int c = 0; c < nCh; ++c) {
        if (c < nCh - 2)      { CP_WAIT2(); }
        else if (c == nCh - 2){ CP_WAIT1(); }
        else                  { CP_WAIT0(); }
        __syncthreads();
        compute_chunk(sb + slot * STG, wm, wn, lane, acc);
        __syncthreads();
        if (c + 3 < nCh) {
            load_chunk(sb + slot * STG, Ah, Al, lda, Bh, Bl, ldb, (c + 3) * 32, tid);
            CP_COMMIT();
        }
        slot = (slot == 2) ? 0 : slot + 1;
    }
}

// ---------------------------------------------------------------------------
// 1) QKV GEMM: z=0->Q(bf16 split), z=1->K(bf16 split), z=2->V(fp32).
//    grid (8, 64, 3)
// ---------------------------------------------------------------------------
__global__ void __launch_bounds__(256, 2) qkv_gemm()
{
    extern __shared__ char smem[];
    const uint32_t sb = smem_u32(smem);
    const int tid = threadIdx.x, lane = tid & 31, w = tid >> 5;
    const int z = blockIdx.z;
    const int n0 = blockIdx.x * 128;
    const int m0 = blockIdx.y * 128;

    float acc[4][4][4];
    gemm_hmma(g_xh + (size_t)m0 * DD, g_xl + (size_t)m0 * DD, DD,
              g_Wth + (size_t)z * DD * DD + (size_t)n0 * DD,
              g_Wtl + (size_t)z * DD * DD + (size_t)n0 * DD, DD,
              32, acc, sb, tid);

    const int tg = lane >> 2, t4 = lane & 3;
    const int wm = w & 1, wn = w >> 1;
#pragma unroll
    for (int i = 0; i < 4; ++i) {
#pragma unroll
        for (int j = 0; j < 4; ++j) {
            const int r = m0 + wm * 64 + i * 16 + tg;
            const int c = n0 + wn * 32 + j * 8 + t4 * 2;
            if (z == 2) {
                *(float2*)(g_V + (size_t)r * DD + c) =
                    make_float2(acc[i][j][0], acc[i][j][1]);
                *(float2*)(g_V + (size_t)(r + 8) * DD + c) =
                    make_float2(acc[i][j][2], acc[i][j][3]);
            } else {
                __nv_bfloat16* dh = (z == 0 ? g_Qh : g_Kh);
                __nv_bfloat16* dl = (z == 0 ? g_Ql : g_Kl);
                uint32_t lo, hi;
                hi = pack2(acc[i][j][0], acc[i][j][1], lo);
                *(uint32_t*)(dh + (size_t)r * DD + c) = hi;
                *(uint32_t*)(dl + (size_t)r * DD + c) = lo;
                hi = pack2(acc[i][j][2], acc[i][j][3], lo);
                *(uint32_t*)(dh + (size_t)(r + 8) * DD + c) = hi;
                *(uint32_t*)(dl + (size_t)(r + 8) * DD + c) = lo;
            }
        }
    }
}

// ---------------------------------------------------------------------------
// 2) Scores: P = scale * Q @ K^T, exactly the causal tiles. grid (136, 4)
// ---------------------------------------------------------------------------
__global__ void __launch_bounds__(256, 2) scores_gemm()
{
    const int t = blockIdx.x, b = blockIdx.y;
    int it = (int)floorf((sqrtf(8.f * (float)t + 1.f) - 1.f) * 0.5f);
    while ((it + 1) * (it + 2) / 2 <= t) ++it;
    while (it * (it + 1) / 2 > t) --it;
    const int jt = t - it * (it + 1) / 2;

    extern __shared__ char smem[];
    const uint32_t sb = smem_u32(smem);
    const int tid = threadIdx.x, lane = tid & 31, w = tid >> 5;

    float acc[4][4][4];
    gemm_hmma(g_Qh + ((size_t)b * SS + it * 128) * DD,
              g_Ql + ((size_t)b * SS + it * 128) * DD, DD,
              g_Kh + ((size_t)b * SS + jt * 128) * DD,
              g_Kl + ((size_t)b * SS + jt * 128) * DD, DD,
              32, acc, sb, tid);

    const int tg = lane >> 2, t4 = lane & 3;
    const int wm = w & 1, wn = w >> 1;
    const float scale = 0.03125f;  // 1/sqrt(1024)
#pragma unroll
    for (int i = 0; i < 4; ++i) {
#pragma unroll
        for (int j = 0; j < 4; ++j) {
            const int r = it * 128 + wm * 64 + i * 16 + tg;
            const int c = jt * 128 + wn * 32 + j * 8 + t4 * 2;
            float* base = g_P + (size_t)b * SS * SS;
            *(float2*)(base + (size_t)r * SS + c) =
                make_float2(acc[i][j][0] * scale, acc[i][j][1] * scale);
            *(float2*)(base + (size_t)(r + 8) * SS + c) =
                make_float2(acc[i][j][2] * scale, acc[i][j][3] * scale);
        }
    }
}

// ---------------------------------------------------------------------------
// 3) PV: O = P @ V (Vt pre-transposed, P split bf16). grid (8, 16, 4)
// ---------------------------------------------------------------------------
__global__ void __launch_bounds__(256, 2) pv_gemm(float* __restrict__ out)
{
    extern __shared__ char smem[];
    const uint32_t sb = smem_u32(smem);
    const int tid = threadIdx.x, lane = tid & 31, w = tid >> 5;
    const int n0 = blockIdx.x * 128;
    const int it = blockIdx.y, b = blockIdx.z;

    float acc[4][4][4];
    gemm_hmma(g_Ph + ((size_t)b * SS + it * 128) * SS,
              g_Pl + ((size_t)b * SS + it * 128) * SS, SS,
              g_Vth + ((size_t)b * DD + n0) * SS,
              g_Vtl + ((size_t)b * DD + n0) * SS, SS,
              (it + 1) * 4, acc, sb, tid);

    const int tg = lane >> 2, t4 = lane & 3;
    const int wm = w & 1, wn = w >> 1;
#pragma unroll
    for (int i = 0; i < 4; ++i) {
#pragma unroll
        for (int j = 0; j < 4; ++j) {
            const size_t r = (size_t)b * SS + it * 128 + wm * 64 + i * 16 + tg;
            const int c = n0 + wn * 32 + j * 8 + t4 * 2;
            *(float2*)(out + r * DD + c) = make_float2(acc[i][j][0], acc[i][j][1]);
            *(float2*)(out + (r + 8) * DD + c) = make_float2(acc[i][j][2], acc[i][j][3]);
        }
    }
}

// ---------------------------------------------------------------------------
// Prep: split x into bf16 hi/lo. grid 8192, block 256 (4 floats/thread)
// ---------------------------------------------------------------------------
__global__ void __launch_bounds__(256) split_x_kernel(const float* __restrict__ in)
{
    size_t i = (size_t)blockIdx.x * 256 + threadIdx.x;
    float4 v = ((const float4*)in)[i];
    uint2 H, L;
    H.x = pack2(v.x, v.y, L.x);
    H.y = pack2(v.z, v.w, L.y);
    ((uint2*)g_xh)[i] = H;
    ((uint2*)g_xl)[i] = L;
}

// ---------------------------------------------------------------------------
// Prep: transpose + split W. grid (32, 32, 3), block (32, 8)
// ---------------------------------------------------------------------------
__global__ void __launch_bounds__(256) prep_w_kernel(
    const float* __restrict__ WQ, const float* __restrict__ WK,
    const float* __restrict__ WV)
{
    __shared__ float t[32][33];
    const float* W = (blockIdx.z == 0) ? WQ : (blockIdx.z == 1) ? WK : WV;
    const int n0 = blockIdx.x * 32, k0 = blockIdx.y * 32;
    const int tx = threadIdx.x, ty = threadIdx.y;
#pragma unroll
    for (int j = 0; j < 32; j += 8)
        t[ty + j][tx] = W[(size_t)(k0 + ty + j) * DD + n0 + tx];
    __syncthreads();
    __nv_bfloat16* oh = g_Wth + (size_t)blockIdx.z * DD * DD;
    __nv_bfloat16* ol = g_Wtl + (size_t)blockIdx.z * DD * DD;
#pragma unroll
    for (int j = 0; j < 32; j += 8) {
        float v = t[tx][ty + j];
        __nv_bfloat16 h = __float2bfloat16(v);
        __nv_bfloat16 l = __float2bfloat16(v - __bfloat162float(h));
        size_t o = (size_t)(n0 + ty + j) * DD + k0 + tx;
        oh[o] = h;
        ol[o] = l;
    }
}

// ---------------------------------------------------------------------------
// V transpose + split: Vt[b][d][s] = V[b*S+s][d]. grid (32, 64, 4), block (32,8)
// ---------------------------------------------------------------------------
__global__ void __launch_bounds__(256) vtrans_kernel()
{
    __shared__ float t[32][33];
    const int b = blockIdx.z;
    const int d0 = blockIdx.x * 32, s0 = blockIdx.y * 32;
    const int tx = threadIdx.x, ty = threadIdx.y;
#pragma unroll
    for (int j = 0; j < 32; j += 8)
        t[ty + j][tx] = g_V[((size_t)b * SS + s0 + ty + j) * DD + d0 + tx];
    __syncthreads();
#pragma unroll
    for (int j = 0; j < 32; j += 8) {
        float v = t[tx][ty + j];
        __nv_bfloat16 h = __float2bfloat16(v);
        __nv_bfloat16 l = __float2bfloat16(v - __bfloat162float(h));
        size_t o = ((size_t)b * DD + d0 + ty + j) * SS + s0 + tx;
        g_Vth[o] = h;
        g_Vtl[o] = l;
    }
}

// ---------------------------------------------------------------------------
// Softmax: fp32 P row -> bf16 hi/lo P, zero-padded to 128-tile edge.
// grid 8192, block 256
// ---------------------------------------------------------------------------
__global__ void __launch_bounds__(256) softmax_kernel()
{
    const int row = blockIdx.x;
    const int b = row >> 11;
    const int i = row & 2047;
    const float* p = g_P + ((size_t)b * SS + i) * SS;
    __nv_bfloat16* ph = g_Ph + ((size_t)b * SS + i) * SS;
    __nv_bfloat16* pl = g_Pl + ((size_t)b * SS + i) * SS;
    const int L = i + 1;
    const int E = ((i >> 7) + 1) << 7;
    const int tid = threadIdx.x;

    __shared__ float red[256];

    float vals[8];
    float m = -INFINITY;
#pragma unroll
    for (int u = 0; u < 8; u++) {
        int j = tid + u * 256;
        vals[u] = (j < L) ? p[j] : -INFINITY;
        m = fmaxf(m, vals[u]);
    }
    red[tid] = m;
    __syncthreads();
    for (int s = 128; s > 0; s >>= 1) {
        if (tid < s) red[tid] = fmaxf(red[tid], red[tid + s]);
        __syncthreads();
    }
    m = red[0];
    __syncthreads();

    float sum = 0.f;
#pragma unroll
    for (int u = 0; u < 8; u++) {
        int j = tid + u * 256;
        vals[u] = (j < L) ? expf(vals[u] - m) : 0.f;
        sum += vals[u];
    }
    red[tid] = sum;
    __syncthreads();
    for (int s = 128; s > 0; s >>= 1) {
        if (tid < s) red[tid] += red[tid + s];
        __syncthreads();
    }
    const float inv = 1.f / red[0];

#pragma unroll
    for (int u = 0; u < 8; u++) {
        int j = tid + u * 256;
        if (j < E) {
            float v = vals[u] * inv;
            __nv_bfloat16 h = __float2bfloat16(v);
            __nv_bfloat16 l = __float2bfloat16(v - __bfloat162float(h));
            ph[j] = h;
            pl[j] = l;
        }
    }
}

// ---------------------------------------------------------------------------
extern "C" void kernel_launch(void* const* d_in, const int* in_sizes, int n_in,
                              void* d_out, int out_size)
{
    (void)in_sizes; (void)n_in; (void)out_size;
    const float* x  = (const float*)d_in[0];
    const float* WQ = (const float*)d_in[1];
    const float* WK = (const float*)d_in[2];
    const float* WV = (const float*)d_in[3];
    float* out = (float*)d_out;

    cudaFuncSetAttribute(qkv_gemm,    cudaFuncAttributeMaxDynamicSharedMemorySize, SM_TOT);
    cudaFuncSetAttribute(scores_gemm, cudaFuncAttributeMaxDynamicSharedMemorySize, SM_TOT);
    cudaFuncSetAttribute(pv_gemm,     cudaFuncAttributeMaxDynamicSharedMemorySize, SM_TOT);

    split_x_kernel<<<8192, 256>>>(x);
    prep_w_kernel<<<dim3(32, 32, 3), dim3(32, 8)>>>(WQ, WK, WV);
    qkv_gemm<<<dim3(8, 64, 3), 256, SM_TOT>>>();
    vtrans_kernel<<<dim3(32, 64, 4), dim3(32, 8)>>>();
    scores_gemm<<<dim3(136, 4), 256, SM_TOT>>>();
    softmax_kernel<<<8192, 256>>>();
    pv_gemm<<<dim3(8, 16, 4), 256, SM_TOT>>>(out);
}

// round 5
// speedup vs baseline: 1.0704x; 1.0704x over previous
#include <cuda_runtime.h>
#include <cuda_bf16.h>
#include <math.h>
#include <stdint.h>

#define BB 4
#define SS 2048
#define DD 1024
#define MT (BB*SS)   // 8192

// ---------------------------------------------------------------------------
// Scratch (device globals)
// ---------------------------------------------------------------------------
__device__ __align__(16) __nv_bfloat16 g_xh[(size_t)MT*DD], g_xl[(size_t)MT*DD];
__device__ __align__(16) __nv_bfloat16 g_Wth[(size_t)3*DD*DD], g_Wtl[(size_t)3*DD*DD];
__device__ __align__(16) __nv_bfloat16 g_Qh[(size_t)MT*DD], g_Ql[(size_t)MT*DD];
__device__ __align__(16) __nv_bfloat16 g_Kh[(size_t)MT*DD], g_Kl[(size_t)MT*DD];
__device__ __align__(16) float        g_V [(size_t)MT*DD];
__device__ __align__(16) __nv_bfloat16 g_Vth[(size_t)BB*DD*SS], g_Vtl[(size_t)BB*DD*SS];
__device__ __align__(16) float        g_P [(size_t)BB*SS*SS];
__device__ __align__(16) __nv_bfloat16 g_Ph[(size_t)BB*SS*SS], g_Pl[(size_t)BB*SS*SS];

// ---------------------------------------------------------------------------
// Helpers
// ---------------------------------------------------------------------------
__device__ __forceinline__ uint32_t smem_u32(const void* p) {
    uint32_t a;
    asm("{ .reg .u64 t; cvta.to.shared.u64 t, %1; cvt.u32.u64 %0, t; }"
        : "=r"(a) : "l"(p));
    return a;
}

// SW128 swizzle on byte offsets (128B rows): bits[6:4] ^= bits[9:7]
#define SWZ(o) ((uint32_t)(o) ^ ((((uint32_t)(o)) >> 3) & 0x70))

#define CP_ASYNC(dst, src) \
    asm volatile("cp.async.cg.shared.global [%0], [%1], 16;" \
                 :: "r"(dst), "l"(__cvta_generic_to_global(src)))
#define CP_COMMIT() asm volatile("cp.async.commit_group;")
#define CP_WAIT0()  asm volatile("cp.async.wait_group 0;")

#define LDM_X4(r, addr) \
    asm volatile("ldmatrix.sync.aligned.m8n8.x4.shared.b16 {%0,%1,%2,%3}, [%4];" \
        : "=r"((r)[0]), "=r"((r)[1]), "=r"((r)[2]), "=r"((r)[3]) : "r"(addr))

#define MMA(d, a, b0v, b1v) \
    asm volatile("mma.sync.aligned.m16n8k16.row.col.f32.bf16.bf16.f32 " \
        "{%0,%1,%2,%3}, {%4,%5,%6,%7}, {%8,%9}, {%0,%1,%2,%3};" \
        : "+f"((d)[0]), "+f"((d)[1]), "+f"((d)[2]), "+f"((d)[3]) \
        : "r"((a)[0]), "r"((a)[1]), "r"((a)[2]), "r"((a)[3]), "r"(b0v), "r"(b1v))

// bf16 2-term split: returns packed hi pair, writes packed lo pair
__device__ __forceinline__ uint32_t pack2(float a, float b, uint32_t& lo2) {
    __nv_bfloat16 ha = __float2bfloat16(a);
    __nv_bfloat16 hb = __float2bfloat16(b);
    __nv_bfloat16 la = __float2bfloat16(a - __bfloat162float(ha));
    __nv_bfloat16 lb = __float2bfloat16(b - __bfloat162float(hb));
    lo2 = (uint32_t)__bfloat16_as_ushort(la) | ((uint32_t)__bfloat16_as_ushort(lb) << 16);
    return (uint32_t)__bfloat16_as_ushort(ha) | ((uint32_t)__bfloat16_as_ushort(hb) << 16);
}

// ---------------------------------------------------------------------------
// SMEM layout: 2 stages x (AH, AL, BH, BL planes of 128x64 bf16 = 16KB each)
// 128KB total -> 1 CTA/SM (regs uncapped)
// ---------------------------------------------------------------------------
#define OFF_AH 0
#define OFF_AL 16384
#define OFF_BH 32768
#define OFF_BL 49152
#define STG    65536
#define SM_TOT (2*STG)   // 131072 bytes

// ---------------------------------------------------------------------------
// Load one BK=64 chunk (all 4 planes) via cp.async. 16 x 16B per thread.
// ---------------------------------------------------------------------------
__device__ __forceinline__ void load_chunk(
    uint32_t stg,
    const __nv_bfloat16* __restrict__ Ah, const __nv_bfloat16* __restrict__ Al, int lda,
    const __nv_bfloat16* __restrict__ Bh, const __nv_bfloat16* __restrict__ Bl, int ldb,
    int k0, int tid)
{
#pragma unroll
    for (int i = 0; i < 4; ++i) {
        int u = tid + i * 256, row = u >> 3, ch = u & 7;
        uint32_t off = SWZ(row * 128 + ch * 16);
        size_t ga = (size_t)row * lda + k0 + ch * 8;
        size_t gb = (size_t)row * ldb + k0 + ch * 8;
        CP_ASYNC(stg + OFF_AH + off, Ah + ga);
        CP_ASYNC(stg + OFF_AL + off, Al + ga);
        CP_ASYNC(stg + OFF_BH + off, Bh + gb);
        CP_ASYNC(stg + OFF_BL + off, Bl + gb);
    }
}

// ---------------------------------------------------------------------------
// Compute one BK=64 chunk: warp tile 64x32, 3-term split HMMA.
// ---------------------------------------------------------------------------
__device__ __forceinline__ void compute_chunk(
    uint32_t stg, int wm, int wn, int lane, float (&acc)[4][4][4])
{
    const int rsel = lane & 15;
    const int csel = lane >> 4;
#pragma unroll
    for (int ks = 0; ks < 4; ++ks) {
        uint32_t ah[4][4], al[4][4], bh[2][4], bl[2][4];
#pragma unroll
        for (int i = 0; i < 4; ++i) {
            uint32_t off = SWZ((wm * 64 + i * 16 + rsel) * 128 + (ks * 2 + csel) * 16);
            LDM_X4(ah[i], stg + OFF_AH + off);
            LDM_X4(al[i], stg + OFF_AL + off);
        }
#pragma unroll
        for (int j2 = 0; j2 < 2; ++j2) {
            uint32_t off = SWZ((wn * 32 + j2 * 16 + rsel) * 128 + (ks * 2 + csel) * 16);
            LDM_X4(bh[j2], stg + OFF_BH + off);
            LDM_X4(bl[j2], stg + OFF_BL + off);
        }
#pragma unroll
        for (int i = 0; i < 4; ++i) {
#pragma unroll
            for (int j = 0; j < 4; ++j) {
                const int j2 = j >> 1, s = j & 1;
                MMA(acc[i][j], ah[i], bh[j2][s], bh[j2][s + 2]);
                MMA(acc[i][j], ah[i], bl[j2][s], bl[j2][s + 2]);
                MMA(acc[i][j], al[i], bh[j2][s], bh[j2][s + 2]);
            }
        }
    }
}

// ---------------------------------------------------------------------------
// Full GEMM mainloop: C[128,128] = sum over nCh chunks of 64.
// Single __syncthreads per chunk: wait -> sync -> issue next load -> compute.
// ---------------------------------------------------------------------------
__device__ __forceinline__ void gemm_hmma(
    const __nv_bfloat16* __restrict__ Ah, const __nv_bfloat16* __restrict__ Al, int lda,
    const __nv_bfloat16* __restrict__ Bh, const __nv_bfloat16* __restrict__ Bl, int ldb,
    int nCh, float (&acc)[4][4][4], uint32_t sb, int tid)
{
    const int lane = tid & 31, w = tid >> 5;
    const int wm = w & 1, wn = w >> 1;

#pragma unroll
    for (int i = 0; i < 4; ++i)
#pragma unroll
        for (int j = 0; j < 4; ++j)
#pragma unroll
            for (int q = 0; q < 4; ++q) acc[i][j][q] = 0.f;

    load_chunk(sb, Ah, Al, lda, Bh, Bl, ldb, 0, tid);
    CP_COMMIT();

    for (int c = 0; c < nCh; ++c) {
        CP_WAIT0();           // this thread's portion of chunk c landed
        __syncthreads();      // all threads' portions landed; prev compute done
        if (c + 1 < nCh) {    // slot (c+1)&1 was freed by compute(c-1)
            load_chunk(sb + ((c + 1) & 1) * STG, Ah, Al, lda, Bh, Bl, ldb,
                       (c + 1) * 64, tid);
            CP_COMMIT();
        }
        compute_chunk(sb + (c & 1) * STG, wm, wn, lane, acc);
    }
}

// ---------------------------------------------------------------------------
// 1) QKV GEMM: z=0->Q(bf16 split), z=1->K(bf16 split), z=2->V(fp32).
//    grid (8, 64, 3)
// ---------------------------------------------------------------------------
__global__ void __launch_bounds__(256) qkv_gemm()
{
    extern __shared__ char smem[];
    const uint32_t sb = smem_u32(smem);
    const int tid = threadIdx.x, lane = tid & 31, w = tid >> 5;
    const int z = blockIdx.z;
    const int n0 = blockIdx.x * 128;
    const int m0 = blockIdx.y * 128;

    float acc[4][4][4];
    gemm_hmma(g_xh + (size_t)m0 * DD, g_xl + (size_t)m0 * DD, DD,
              g_Wth + (size_t)z * DD * DD + (size_t)n0 * DD,
              g_Wtl + (size_t)z * DD * DD + (size_t)n0 * DD, DD,
              16, acc, sb, tid);

    const int tg = lane >> 2, t4 = lane & 3;
    const int wm = w & 1, wn = w >> 1;
#pragma unroll
    for (int i = 0; i < 4; ++i) {
#pragma unroll
        for (int j = 0; j < 4; ++j) {
            const int r = m0 + wm * 64 + i * 16 + tg;
            const int c = n0 + wn * 32 + j * 8 + t4 * 2;
            if (z == 2) {
                *(float2*)(g_V + (size_t)r * DD + c) =
                    make_float2(acc[i][j][0], acc[i][j][1]);
                *(float2*)(g_V + (size_t)(r + 8) * DD + c) =
                    make_float2(acc[i][j][2], acc[i][j][3]);
            } else {
                __nv_bfloat16* dh = (z == 0 ? g_Qh : g_Kh);
                __nv_bfloat16* dl = (z == 0 ? g_Ql : g_Kl);
                uint32_t lo, hi;
                hi = pack2(acc[i][j][0], acc[i][j][1], lo);
                *(uint32_t*)(dh + (size_t)r * DD + c) = hi;
                *(uint32_t*)(dl + (size_t)r * DD + c) = lo;
                hi = pack2(acc[i][j][2], acc[i][j][3], lo);
                *(uint32_t*)(dh + (size_t)(r + 8) * DD + c) = hi;
                *(uint32_t*)(dl + (size_t)(r + 8) * DD + c) = lo;
            }
        }
    }
}

// ---------------------------------------------------------------------------
// 2) Scores: P = scale * Q @ K^T, exactly the causal tiles. grid (136, 4)
// ---------------------------------------------------------------------------
__global__ void __launch_bounds__(256) scores_gemm()
{
    const int t = blockIdx.x, b = blockIdx.y;
    int it = (int)floorf((sqrtf(8.f * (float)t + 1.f) - 1.f) * 0.5f);
    while ((it + 1) * (it + 2) / 2 <= t) ++it;
    while (it * (it + 1) / 2 > t) --it;
    const int jt = t - it * (it + 1) / 2;

    extern __shared__ char smem[];
    const uint32_t sb = smem_u32(smem);
    const int tid = threadIdx.x, lane = tid & 31, w = tid >> 5;

    float acc[4][4][4];
    gemm_hmma(g_Qh + ((size_t)b * SS + it * 128) * DD,
              g_Ql + ((size_t)b * SS + it * 128) * DD, DD,
              g_Kh + ((size_t)b * SS + jt * 128) * DD,
              g_Kl + ((size_t)b * SS + jt * 128) * DD, DD,
              16, acc, sb, tid);

    const int tg = lane >> 2, t4 = lane & 3;
    const int wm = w & 1, wn = w >> 1;
    const float scale = 0.03125f;  // 1/sqrt(1024)
#pragma unroll
    for (int i = 0; i < 4; ++i) {
#pragma unroll
        for (int j = 0; j < 4; ++j) {
            const int r = it * 128 + wm * 64 + i * 16 + tg;
            const int c = jt * 128 + wn * 32 + j * 8 + t4 * 2;
            float* base = g_P + (size_t)b * SS * SS;
            *(float2*)(base + (size_t)r * SS + c) =
                make_float2(acc[i][j][0] * scale, acc[i][j][1] * scale);
            *(float2*)(base + (size_t)(r + 8) * SS + c) =
                make_float2(acc[i][j][2] * scale, acc[i][j][3] * scale);
        }
    }
}

// ---------------------------------------------------------------------------
// 3) PV: O = P @ V. Heavy row-blocks first (LPT scheduling). grid (8, 16, 4)
// ---------------------------------------------------------------------------
__global__ void __launch_bounds__(256) pv_gemm(float* __restrict__ out)
{
    extern __shared__ char smem[];
    const uint32_t sb = smem_u32(smem);
    const int tid = threadIdx.x, lane = tid & 31, w = tid >> 5;
    const int n0 = blockIdx.x * 128;
    const int it = 15 - blockIdx.y;   // heavy-first
    const int b = blockIdx.z;

    float acc[4][4][4];
    gemm_hmma(g_Ph + ((size_t)b * SS + it * 128) * SS,
              g_Pl + ((size_t)b * SS + it * 128) * SS, SS,
              g_Vth + ((size_t)b * DD + n0) * SS,
              g_Vtl + ((size_t)b * DD + n0) * SS, SS,
              (it + 1) * 2, acc, sb, tid);

    const int tg = lane >> 2, t4 = lane & 3;
    const int wm = w & 1, wn = w >> 1;
#pragma unroll
    for (int i = 0; i < 4; ++i) {
#pragma unroll
        for (int j = 0; j < 4; ++j) {
            const size_t r = (size_t)b * SS + it * 128 + wm * 64 + i * 16 + tg;
            const int c = n0 + wn * 32 + j * 8 + t4 * 2;
            *(float2*)(out + r * DD + c) = make_float2(acc[i][j][0], acc[i][j][1]);
            *(float2*)(out + (r + 8) * DD + c) = make_float2(acc[i][j][2], acc[i][j][3]);
        }
    }
}

// ---------------------------------------------------------------------------
// Prep: split x into bf16 hi/lo. grid 8192, block 256 (4 floats/thread)
// ---------------------------------------------------------------------------
__global__ void __launch_bounds__(256) split_x_kernel(const float* __restrict__ in)
{
    size_t i = (size_t)blockIdx.x * 256 + threadIdx.x;
    float4 v = ((const float4*)in)[i];
    uint2 H, L;
    H.x = pack2(v.x, v.y, L.x);
    H.y = pack2(v.z, v.w, L.y);
    ((uint2*)g_xh)[i] = H;
    ((uint2*)g_xl)[i] = L;
}

// ---------------------------------------------------------------------------
// Prep: transpose + split W. grid (32, 32, 3), block (32, 8)
// ---------------------------------------------------------------------------
__global__ void __launch_bounds__(256) prep_w_kernel(
    const float* __restrict__ WQ, const float* __restrict__ WK,
    const float* __restrict__ WV)
{
    __shared__ float t[32][33];
    const float* W = (blockIdx.z == 0) ? WQ : (blockIdx.z == 1) ? WK : WV;
    const int n0 = blockIdx.x * 32, k0 = blockIdx.y * 32;
    const int tx = threadIdx.x, ty = threadIdx.y;
#pragma unroll
    for (int j = 0; j < 32; j += 8)
        t[ty + j][tx] = W[(size_t)(k0 + ty + j) * DD + n0 + tx];
    __syncthreads();
    __nv_bfloat16* oh = g_Wth + (size_t)blockIdx.z * DD * DD;
    __nv_bfloat16* ol = g_Wtl + (size_t)blockIdx.z * DD * DD;
#pragma unroll
    for (int j = 0; j < 32; j += 8) {
        float v = t[tx][ty + j];
        __nv_bfloat16 h = __float2bfloat16(v);
        __nv_bfloat16 l = __float2bfloat16(v - __bfloat162float(h));
        size_t o = (size_t)(n0 + ty + j) * DD + k0 + tx;
        oh[o] = h;
        ol[o] = l;
    }
}

// ---------------------------------------------------------------------------
// V transpose + split: Vt[b][d][s] = V[b*S+s][d]. grid (32, 64, 4), block (32,8)
// ---------------------------------------------------------------------------
__global__ void __launch_bounds__(256) vtrans_kernel()
{
    __shared__ float t[32][33];
    const int b = blockIdx.z;
    const int d0 = blockIdx.x * 32, s0 = blockIdx.y * 32;
    const int tx = threadIdx.x, ty = threadIdx.y;
#pragma unroll
    for (int j = 0; j < 32; j += 8)
        t[ty + j][tx] = g_V[((size_t)b * SS + s0 + ty + j) * DD + d0 + tx];
    __syncthreads();
#pragma unroll
    for (int j = 0; j < 32; j += 8) {
        float v = t[tx][ty + j];
        __nv_bfloat16 h = __float2bfloat16(v);
        __nv_bfloat16 l = __float2bfloat16(v - __bfloat162float(h));
        size_t o = ((size_t)b * DD + d0 + ty + j) * SS + s0 + tx;
        g_Vth[o] = h;
        g_Vtl[o] = l;
    }
}

// ---------------------------------------------------------------------------
// Softmax: fp32 P row -> bf16 hi/lo P, zero-padded to 128-tile edge.
// Each thread owns 8 consecutive elements (vectorized IO). grid 8192, block 256
// ---------------------------------------------------------------------------
__global__ void __launch_bounds__(256) softmax_kernel()
{
    const int row = blockIdx.x;
    const int b = row >> 11;
    const int i = row & 2047;
    const float* p = g_P + ((size_t)b * SS + i) * SS;
    __nv_bfloat16* ph = g_Ph + ((size_t)b * SS + i) * SS;
    __nv_bfloat16* pl = g_Pl + ((size_t)b * SS + i) * SS;
    const int L = i + 1;
    const int E = ((i >> 7) + 1) << 7;
    const int tid = threadIdx.x;
    const int base = tid * 8;

    __shared__ float red[256];

    float vals[8];
    {
        float4 v0 = ((const float4*)p)[tid * 2];
        float4 v1 = ((const float4*)p)[tid * 2 + 1];
        vals[0] = v0.x; vals[1] = v0.y; vals[2] = v0.z; vals[3] = v0.w;
        vals[4] = v1.x; vals[5] = v1.y; vals[6] = v1.z; vals[7] = v1.w;
    }
    float m = -INFINITY;
#pragma unroll
    for (int u = 0; u < 8; u++) {
        if (base + u >= L) vals[u] = -INFINITY;
        m = fmaxf(m, vals[u]);
    }
    red[tid] = m;
    __syncthreads();
    for (int s = 128; s > 0; s >>= 1) {
        if (tid < s) red[tid] = fmaxf(red[tid], red[tid + s]);
        __syncthreads();
    }
    m = red[0];
    __syncthreads();

    float sum = 0.f;
#pragma unroll
    for (int u = 0; u < 8; u++) {
        vals[u] = (base + u < L) ? expf(vals[u] - m) : 0.f;
        sum += vals[u];
    }
    red[tid] = sum;
    __syncthreads();
    for (int s = 128; s > 0; s >>= 1) {
        if (tid < s) red[tid] += red[tid + s];
        __syncthreads();
    }
    const float inv = 1.f / red[0];

    if (base < E) {
        uint4 H, L4;
        H.x = pack2(vals[0] * inv, vals[1] * inv, L4.x);
        H.y = pack2(vals[2] * inv, vals[3] * inv, L4.y);
        H.z = pack2(vals[4] * inv, vals[5] * inv, L4.z);
        H.w = pack2(vals[6] * inv, vals[7] * inv, L4.w);
        *(uint4*)(ph + base) = H;
        *(uint4*)(pl + base) = L4;
    }
}

// ---------------------------------------------------------------------------
extern "C" void kernel_launch(void* const* d_in, const int* in_sizes, int n_in,
                              void* d_out, int out_size)
{
    (void)in_sizes; (void)n_in; (void)out_size;
    const float* x  = (const float*)d_in[0];
    const float* WQ = (const float*)d_in[1];
    const float* WK = (const float*)d_in[2];
    const float* WV = (const float*)d_in[3];
    float* out = (float*)d_out;

    cudaFuncSetAttribute(qkv_gemm,    cudaFuncAttributeMaxDynamicSharedMemorySize, SM_TOT);
    cudaFuncSetAttribute(scores_gemm, cudaFuncAttributeMaxDynamicSharedMemorySize, SM_TOT);
    cudaFuncSetAttribute(pv_gemm,     cudaFuncAttributeMaxDynamicSharedMemorySize, SM_TOT);

    split_x_kernel<<<8192, 256>>>(x);
    prep_w_kernel<<<dim3(32, 32, 3), dim3(32, 8)>>>(WQ, WK, WV);
    qkv_gemm<<<dim3(8, 64, 3), 256, SM_TOT>>>();
    vtrans_kernel<<<dim3(32, 64, 4), dim3(32, 8)>>>();
    scores_gemm<<<dim3(136, 4), 256, SM_TOT>>>();
    softmax_kernel<<<8192, 256>>>();
    pv_gemm<<<dim3(8, 16, 4), 256, SM_TOT>>>(out);
}